// round 1
// baseline (speedup 1.0000x reference)
#include <cuda_runtime.h>
#include <math_constants.h>

#define BSZ 16
#define SEQ 2048
#define DK  64
#define BM  64
#define BN  64

// Scratch: transposed Q and K, [b][d][s]  (device globals = sanctioned scratch)
__device__ float g_QT[BSZ * DK * SEQ];
__device__ float g_KT[BSZ * DK * SEQ];

// [b][s][d] -> [b][d][s]
__global__ void transpose_kernel(const float* __restrict__ in, int which) {
    __shared__ float tile[32][33];
    int b  = blockIdx.z;
    int s0 = blockIdx.x * 32;
    int d0 = blockIdx.y * 32;
    int tx = threadIdx.x, ty = threadIdx.y;
    const float* ip = in + (size_t)b * SEQ * DK;
    float* op = (which ? g_KT : g_QT) + (size_t)b * DK * SEQ;
    #pragma unroll
    for (int i = ty; i < 32; i += 8)
        tile[i][tx] = ip[(s0 + i) * DK + (d0 + tx)];
    __syncthreads();
    #pragma unroll
    for (int i = ty; i < 32; i += 8)
        op[(d0 + i) * SEQ + (s0 + tx)] = tile[tx][i];
}

__global__ __launch_bounds__(256, 2)
void attn_kernel(const float* __restrict__ V,
                 const float* __restrict__ Kr,
                 float* __restrict__ out) {
    extern __shared__ float smem[];
    float* qT  = smem;            // [64][64]  qT[k][uu]
    float* kT  = qT  + 64 * 64;   // [64][64]  kT[k][tt]
    float* vs  = kT  + 64 * 64;   // [64][64]  vs[tt][d]
    float* as_ = vs  + 64 * 64;   // [64][64]  A tile row-major
    float* kr  = as_ + 64 * 64;   // [64][128] kr[k][ci]

    int b   = blockIdx.y;
    int u0  = (int)(gridDim.x - 1 - blockIdx.x) * BM;  // big blocks first
    int tid = threadIdx.x;
    int tx  = tid & 15, ty = tid >> 4;
    int r0  = ty << 2, c0 = tx << 2;

    const float* QTb = g_QT + (size_t)b * DK * SEQ;
    const float* KTb = g_KT + (size_t)b * DK * SEQ;
    const float* Vb  = V    + (size_t)b * SEQ * DK;

    // Q tile, loaded once (k-major)
    #pragma unroll
    for (int x = tid; x < 64 * 16; x += 256) {
        int row = x >> 4, col = (x & 15) << 2;
        *(float4*)&qT[row * 64 + col] = *(const float4*)&QTb[row * SEQ + u0 + col];
    }

    float m_i[4], l_i[4], o[16];
    #pragma unroll
    for (int i = 0; i < 4; i++) { m_i[i] = -CUDART_INF_F; l_i[i] = 0.f; }
    #pragma unroll
    for (int i = 0; i < 16; i++) o[i] = 0.f;

    const int nIter = u0 / BN + 1;
    for (int it = 0; it < nIter; ++it) {
        const int t0 = it * BN;
        __syncthreads();  // protect smem reuse from previous iteration

        // K tile (k-major) and V tile (row-major)
        #pragma unroll
        for (int x = tid; x < 64 * 16; x += 256) {
            int row = x >> 4, col = (x & 15) << 2;
            *(float4*)&kT[row * 64 + col] = *(const float4*)&KTb[row * SEQ + t0 + col];
            *(float4*)&vs[row * 64 + col] = *(const float4*)&Vb[(t0 + row) * DK + col];
        }
        // Relpos window: columns c_lo .. c_lo+127 of Krelpos (d-major already)
        const int c_lo = SEQ - BN - u0 + t0;
        #pragma unroll
        for (int x = tid; x < 64 * 32; x += 256) {
            int row = x >> 5, col = (x & 31) << 2;
            int c = c_lo + col;
            if (c + 3 <= SEQ - 1) {
                *(float4*)&kr[row * 128 + col] = *(const float4*)&Kr[row * SEQ + c];
            } else {  // clamp (values only land in masked region)
                float4 t;
                t.x = Kr[row * SEQ + min(c + 0, SEQ - 1)];
                t.y = Kr[row * SEQ + min(c + 1, SEQ - 1)];
                t.z = Kr[row * SEQ + min(c + 2, SEQ - 1)];
                t.w = Kr[row * SEQ + min(c + 3, SEQ - 1)];
                *(float4*)&kr[row * 128 + col] = t;
            }
        }
        __syncthreads();

        // S = Q K^T + Q Krel(window), 4x4 micro-tile per thread
        float s[16];
        #pragma unroll
        for (int i = 0; i < 16; i++) s[i] = 0.f;
        const int cb = c0 - r0 + 60;  // multiple of 4 -> aligned float4 window
        #pragma unroll 8
        for (int k = 0; k < 64; k++) {
            float4 q4  = *(const float4*)&qT[k * 64 + r0];
            float4 k4  = *(const float4*)&kT[k * 64 + c0];
            float4 kr0 = *(const float4*)&kr[k * 128 + cb];
            float4 kr1 = *(const float4*)&kr[k * 128 + cb + 4];
            float qv[4]  = {q4.x, q4.y, q4.z, q4.w};
            float kv[4]  = {k4.x, k4.y, k4.z, k4.w};
            float krv[8] = {kr0.x, kr0.y, kr0.z, kr0.w, kr1.x, kr1.y, kr1.z, kr1.w};
            #pragma unroll
            for (int i = 0; i < 4; i++)
                #pragma unroll
                for (int j = 0; j < 4; j++) {
                    s[i * 4 + j] = fmaf(qv[i], kv[j], s[i * 4 + j]);
                    s[i * 4 + j] = fmaf(qv[i], krv[j - i + 3], s[i * 4 + j]);
                }
        }
        #pragma unroll
        for (int i = 0; i < 16; i++) s[i] *= 0.125f;  // 1/sqrt(64)

        if (t0 == u0) {  // diagonal tile: causal mask
            #pragma unroll
            for (int i = 0; i < 4; i++)
                #pragma unroll
                for (int j = 0; j < 4; j++)
                    if (c0 + j > r0 + i) s[i * 4 + j] = -CUDART_INF_F;
        }

        // Online softmax per row (rows replicated across the 16 tx lanes)
        #pragma unroll
        for (int i = 0; i < 4; i++) {
            float rm = fmaxf(fmaxf(s[i * 4 + 0], s[i * 4 + 1]),
                             fmaxf(s[i * 4 + 2], s[i * 4 + 3]));
            #pragma unroll
            for (int off = 1; off < 16; off <<= 1)
                rm = fmaxf(rm, __shfl_xor_sync(0xffffffffu, rm, off));
            float mn    = fmaxf(m_i[i], rm);
            float alpha = __expf(m_i[i] - mn);
            m_i[i] = mn;
            float ps = 0.f;
            #pragma unroll
            for (int j = 0; j < 4; j++) {
                float p = __expf(s[i * 4 + j] - mn);
                s[i * 4 + j] = p;
                ps += p;
            }
            #pragma unroll
            for (int off = 1; off < 16; off <<= 1)
                ps += __shfl_xor_sync(0xffffffffu, ps, off);
            l_i[i] = l_i[i] * alpha + ps;
            #pragma unroll
            for (int j = 0; j < 4; j++) o[i * 4 + j] *= alpha;
            float4 pv = make_float4(s[i * 4 + 0], s[i * 4 + 1], s[i * 4 + 2], s[i * 4 + 3]);
            *(float4*)&as_[(r0 + i) * 64 + c0] = pv;
        }
        __syncthreads();

        // O += A @ V   (4 rows x 4 output cols, 4-wide tt chunks)
        #pragma unroll 4
        for (int tt = 0; tt < 64; tt += 4) {
            float4 a0 = *(const float4*)&as_[(r0 + 0) * 64 + tt];
            float4 a1 = *(const float4*)&as_[(r0 + 1) * 64 + tt];
            float4 a2 = *(const float4*)&as_[(r0 + 2) * 64 + tt];
            float4 a3 = *(const float4*)&as_[(r0 + 3) * 64 + tt];
            float4 v0 = *(const float4*)&vs[(tt + 0) * 64 + c0];
            float4 v1 = *(const float4*)&vs[(tt + 1) * 64 + c0];
            float4 v2 = *(const float4*)&vs[(tt + 2) * 64 + c0];
            float4 v3 = *(const float4*)&vs[(tt + 3) * 64 + c0];
            float av[4][4] = {{a0.x, a0.y, a0.z, a0.w}, {a1.x, a1.y, a1.z, a1.w},
                              {a2.x, a2.y, a2.z, a2.w}, {a3.x, a3.y, a3.z, a3.w}};
            float vv[4][4] = {{v0.x, v0.y, v0.z, v0.w}, {v1.x, v1.y, v1.z, v1.w},
                              {v2.x, v2.y, v2.z, v2.w}, {v3.x, v3.y, v3.z, v3.w}};
            #pragma unroll
            for (int i = 0; i < 4; i++)
                #pragma unroll
                for (int q = 0; q < 4; q++)
                    #pragma unroll
                    for (int j = 0; j < 4; j++)
                        o[i * 4 + j] = fmaf(av[i][q], vv[q][j], o[i * 4 + j]);
        }
    }

    // Epilogue: normalize and store
    float* ob = out + (size_t)b * SEQ * DK;
    #pragma unroll
    for (int i = 0; i < 4; i++) {
        float inv = 1.f / l_i[i];
        float4 r;
        r.x = o[i * 4 + 0] * inv;
        r.y = o[i * 4 + 1] * inv;
        r.z = o[i * 4 + 2] * inv;
        r.w = o[i * 4 + 3] * inv;
        *(float4*)&ob[(size_t)(u0 + r0 + i) * DK + c0] = r;
    }
}

extern "C" void kernel_launch(void* const* d_in, const int* in_sizes, int n_in,
                              void* d_out, int out_size) {
    const float* Q  = (const float*)d_in[0];
    const float* K  = (const float*)d_in[1];
    const float* V  = (const float*)d_in[2];
    const float* Kr = (const float*)d_in[3];
    float* out = (float*)d_out;

    cudaFuncSetAttribute(attn_kernel, cudaFuncAttributeMaxDynamicSharedMemorySize, 98304);

    dim3 tb(32, 8);
    dim3 tg(SEQ / 32, DK / 32, BSZ);
    transpose_kernel<<<tg, tb>>>(Q, 0);
    transpose_kernel<<<tg, tb>>>(K, 1);

    attn_kernel<<<dim3(SEQ / BM, BSZ), 256, 98304>>>(V, Kr, out);
}